// round 8
// baseline (speedup 1.0000x reference)
#include <cuda_runtime.h>
#include <cuda_bf16.h>
#include <cstdint>

#define N_NODES 50000
#define N_EDGES 800000
#define IN_NF 21
#define HID 64
#define OUT_NF 20
#define N_LAYERS 4

// ---------------- scratch (device globals; no runtime allocation) -------------
__device__ float g_h[N_NODES * HID];
__device__ float g_x[N_NODES * 3];
__device__ float g_cnt[N_NODES];
__device__ float g_agg[N_NODES * HID];
__device__ float g_cagg[N_NODES * 3];

__device__ __forceinline__ float silu(float v) {
    return v / (1.0f + __expf(-v));
}

#define SWZ(off) ((off) ^ (((off) >> 3) & 0x70))

__device__ __forceinline__ uint32_t smem_u32(const void* p) {
    uint32_t a;
    asm("{ .reg .u64 t; cvta.to.shared.u64 t, %1; cvt.u32.u64 %0, t; }"
        : "=r"(a) : "l"(p));
    return a;
}

// pack two fp32 -> bf16x2 (v0 -> low 16 bits)
__device__ __forceinline__ uint32_t bf16x2_pack(float v0, float v1) {
    uint32_t r;
    asm("cvt.rn.bf16x2.f32 %0, %1, %2;" : "=r"(r) : "f"(v1), "f"(v0));
    return r;
}
__device__ __forceinline__ void split2(float v0, float v1, uint32_t& h, uint32_t& l) {
    h = bf16x2_pack(v0, v1);
    float h0 = __uint_as_float(h << 16);
    float h1 = __uint_as_float(h & 0xFFFF0000u);
    l = bf16x2_pack(v0 - h0, v1 - h1);
}

__device__ __forceinline__ void ldsm4(uint32_t addr, uint32_t r[4]) {
    asm volatile("ldmatrix.sync.aligned.m8n8.x4.shared.b16 {%0,%1,%2,%3}, [%4];"
        : "=r"(r[0]), "=r"(r[1]), "=r"(r[2]), "=r"(r[3]) : "r"(addr));
}
__device__ __forceinline__ void mma16816(float* c, const uint32_t* a, const uint32_t* b) {
    asm volatile(
        "mma.sync.aligned.m16n8k16.row.col.f32.bf16.bf16.f32 "
        "{%0,%1,%2,%3}, {%4,%5,%6,%7}, {%8,%9}, {%0,%1,%2,%3};"
        : "+f"(c[0]), "+f"(c[1]), "+f"(c[2]), "+f"(c[3])
        : "r"(a[0]), "r"(a[1]), "r"(a[2]), "r"(a[3]), "r"(b[0]), "r"(b[1]));
}

// ---------------- small kernels ------------------------------------------------
__global__ void init_kernel(const float* __restrict__ x_in) {
    int i = blockIdx.x * blockDim.x + threadIdx.x;
    if (i < N_NODES * 3) g_x[i] = x_in[i];
    if (i < N_NODES) g_cnt[i] = 0.0f;
}

__global__ void embed_kernel(const float* __restrict__ h_in,
                             const float* __restrict__ W,
                             const float* __restrict__ b) {
    int i = blockIdx.x * blockDim.x + threadIdx.x;
    if (i >= N_NODES * HID) return;
    int n = i >> 6;
    int c = i & 63;
    const float* hr = h_in + n * IN_NF;
    float acc = b[c];
    #pragma unroll
    for (int k = 0; k < IN_NF; k++) acc = fmaf(hr[k], W[k * HID + c], acc);
    g_h[i] = acc;
}

__global__ void count_kernel(const int* __restrict__ row) {
    int e = blockIdx.x * blockDim.x + threadIdx.x;
    if (e < N_EDGES) atomicAdd(&g_cnt[row[e]], 1.0f);
}

__global__ void zero_kernel() {
    int stride = gridDim.x * blockDim.x;
    for (int i = blockIdx.x * blockDim.x + threadIdx.x; i < N_NODES * HID; i += stride)
        g_agg[i] = 0.0f;
    for (int i = blockIdx.x * blockDim.x + threadIdx.x; i < N_NODES * 3; i += stride)
        g_cagg[i] = 0.0f;
}

// ================= edge kernel: mma.sync bf16, 128-edge tiles ==================
// smem byte offsets; all panels [rows][64] bf16, 128B/row, SW128 swizzled.
#define SM_W1A_HI  0
#define SM_W1A_LO  8192
#define SM_W1B_HI  16384
#define SM_W1B_LO  24576
#define SM_W2_HI   32768
#define SM_W2_LO   40960
#define SM_CW1_HI  49152
#define SM_CW1_LO  57344
#define SM_A1R_HI  65536
#define SM_A1R_LO  81920
#define SM_A1C_HI  98304
#define SM_A1C_LO  114688
#define SM_A2_HI   131072
#define SM_A2_LO   147456
#define SM_EP1     163840
#define SM_B2F     164352
#define SM_EP3     164608
#define SM_RAD     165120
#define SM_RIDX    165632
#define SM_DIFF    166144
#define SM_TOTAL_E 167680

#define EK_THREADS 128
#define E_TILES (N_EDGES / 128)   // 6250 exact
#define EK_GRID 152

// 3-pass split-bf16 GEMM over one K=64 panel: C += A*B^T (+ AhBl + AlBh)
// A panel: [128 rows][64 k]; B panel: [64 n][64 k]. Warp handles rows
// [mBase, mBase+32). c[mt][nt][4] fragments.
__device__ __forceinline__ void gemm_panel(float c[2][8][4],
                                           uint32_t aHi, uint32_t aLo,
                                           uint32_t bHi, uint32_t bLo,
                                           int mBase, int lane) {
    int g = lane >> 3, r = lane & 7;
    int aRow  = mBase + ((g & 1) << 3) + r;     // + mt*16
    int aKoff = (g >> 1) << 4;                  // 0 / 16 bytes
    int bRow  = ((g >> 1) << 3) + r;            // + nt2*16
    int bKoff = (g & 1) << 4;
    #pragma unroll
    for (int kt = 0; kt < 4; kt++) {
        int kb = kt << 5;                       // 32 bytes per k16
        #pragma unroll
        for (int combo = 0; combo < 3; combo++) {
            uint32_t aOff = (combo == 2) ? aLo : aHi;
            uint32_t bOff = (combo == 1) ? bLo : bHi;
            uint32_t a0[4], a1[4], b[4][4];
            ldsm4(aOff + SWZ((uint32_t)(aRow * 128 + kb + aKoff)), a0);
            ldsm4(aOff + SWZ((uint32_t)((aRow + 16) * 128 + kb + aKoff)), a1);
            #pragma unroll
            for (int nt2 = 0; nt2 < 4; nt2++)
                ldsm4(bOff + SWZ((uint32_t)((bRow + nt2 * 16) * 128 + kb + bKoff)), b[nt2]);
            #pragma unroll
            for (int nt2 = 0; nt2 < 4; nt2++) {
                mma16816(c[0][2 * nt2],     a0, &b[nt2][0]);
                mma16816(c[0][2 * nt2 + 1], a0, &b[nt2][2]);
                mma16816(c[1][2 * nt2],     a1, &b[nt2][0]);
                mma16816(c[1][2 * nt2 + 1], a1, &b[nt2][2]);
            }
        }
    }
}

__global__ __launch_bounds__(EK_THREADS, 1) void edge_mma_kernel(
    const int* __restrict__ row, const int* __restrict__ col,
    const float* __restrict__ W1, const float* __restrict__ B1,
    const float* __restrict__ W2, const float* __restrict__ B2,
    const float* __restrict__ CW1, const float* __restrict__ CB1,
    const float* __restrict__ CW2)
{
    extern __shared__ char smem[];
    uint32_t sb = smem_u32(smem);
    int tid  = threadIdx.x;
    int lane = tid & 31;
    int wid  = tid >> 5;
    int wrow = wid * 32;

    // ---- stage weights transposed + split: panels [n][k] bf16, SW128 ----
    for (int idx = tid; idx < 8192; idx += EK_THREADS) {
        int k = idx >> 6, n = idx & 63;
        float v = W1[k * 64 + n];
        __nv_bfloat16 hb = __float2bfloat16(v);
        __nv_bfloat16 lb = __float2bfloat16(v - __bfloat162float(hb));
        uint32_t off = SWZ((uint32_t)(n * 128 + (k & 63) * 2));
        int bhi = (k < 64) ? SM_W1A_HI : SM_W1B_HI;
        int blo = (k < 64) ? SM_W1A_LO : SM_W1B_LO;
        *(__nv_bfloat16*)(smem + bhi + off) = hb;
        *(__nv_bfloat16*)(smem + blo + off) = lb;
    }
    for (int idx = tid; idx < 4096; idx += EK_THREADS) {
        int k = idx >> 6, n = idx & 63;
        uint32_t off = SWZ((uint32_t)(n * 128 + k * 2));
        {
            float v = W2[k * 64 + n];
            __nv_bfloat16 hb = __float2bfloat16(v);
            __nv_bfloat16 lb = __float2bfloat16(v - __bfloat162float(hb));
            *(__nv_bfloat16*)(smem + SM_W2_HI + off) = hb;
            *(__nv_bfloat16*)(smem + SM_W2_LO + off) = lb;
        }
        {
            float v = CW1[k * 64 + n];
            __nv_bfloat16 hb = __float2bfloat16(v);
            __nv_bfloat16 lb = __float2bfloat16(v - __bfloat162float(hb));
            *(__nv_bfloat16*)(smem + SM_CW1_HI + off) = hb;
            *(__nv_bfloat16*)(smem + SM_CW1_LO + off) = lb;
        }
    }
    if (tid < 64) {
        ((float2*)(smem + SM_EP1))[tid] = make_float2(B1[tid], W1[128 * 64 + tid]);
        ((float*)(smem + SM_B2F))[tid]  = B2[tid];
        ((float2*)(smem + SM_EP3))[tid] = make_float2(CB1[tid], CW2[tid]);
    }
    __syncthreads();

    const float2* ep1  = (const float2*)(smem + SM_EP1);
    const float*  b2f  = (const float*)(smem + SM_B2F);
    const float2* ep3  = (const float2*)(smem + SM_EP3);
    float* sRad  = (float*)(smem + SM_RAD);
    int*   sRidx = (int*)(smem + SM_RIDX);
    float* sDiff = (float*)(smem + SM_DIFF);

    int qr = lane >> 2;          // 0..7
    int qc = (lane & 3) << 1;    // col base within n8

    for (int tile = blockIdx.x; tile < E_TILES; tile += gridDim.x) {
        // ---- gather: thread t = edge/row t of the tile ----
        {
            int e  = tile * 128 + tid;
            int rr = __ldg(&row[e]);
            int cc = __ldg(&col[e]);
            float d0 = __ldg(&g_x[rr * 3 + 0]) - __ldg(&g_x[cc * 3 + 0]);
            float d1 = __ldg(&g_x[rr * 3 + 1]) - __ldg(&g_x[cc * 3 + 1]);
            float d2 = __ldg(&g_x[rr * 3 + 2]) - __ldg(&g_x[cc * 3 + 2]);
            sRad[tid]  = d0 * d0 + d1 * d1 + d2 * d2;
            sRidx[tid] = rr;
            sDiff[tid * 3 + 0] = d0;
            sDiff[tid * 3 + 1] = d1;
            sDiff[tid * 3 + 2] = d2;
            const float4* hr4 = (const float4*)(g_h + rr * 64);
            const float4* hc4 = (const float4*)(g_h + cc * 64);
            #pragma unroll
            for (int j = 0; j < 8; j++) {
                uint32_t off = SWZ((uint32_t)(tid * 128 + j * 16));
                float4 f0 = __ldg(&hr4[2 * j]);
                float4 f1 = __ldg(&hr4[2 * j + 1]);
                uint32_t h0, h1, h2, h3, l0, l1, l2, l3;
                split2(f0.x, f0.y, h0, l0); split2(f0.z, f0.w, h1, l1);
                split2(f1.x, f1.y, h2, l2); split2(f1.z, f1.w, h3, l3);
                *(uint4*)(smem + SM_A1R_HI + off) = make_uint4(h0, h1, h2, h3);
                *(uint4*)(smem + SM_A1R_LO + off) = make_uint4(l0, l1, l2, l3);
                f0 = __ldg(&hc4[2 * j]);
                f1 = __ldg(&hc4[2 * j + 1]);
                split2(f0.x, f0.y, h0, l0); split2(f0.z, f0.w, h1, l1);
                split2(f1.x, f1.y, h2, l2); split2(f1.z, f1.w, h3, l3);
                *(uint4*)(smem + SM_A1C_HI + off) = make_uint4(h0, h1, h2, h3);
                *(uint4*)(smem + SM_A1C_LO + off) = make_uint4(l0, l1, l2, l3);
            }
        }
        __syncthreads();

        float c[2][8][4];

        // ---- GEMM1: feat @ W1 (two K=64 panels) ----
        #pragma unroll
        for (int mt = 0; mt < 2; mt++)
            #pragma unroll
            for (int nt = 0; nt < 8; nt++)
                #pragma unroll
                for (int q = 0; q < 4; q++) c[mt][nt][q] = 0.0f;
        gemm_panel(c, sb + SM_A1R_HI, sb + SM_A1R_LO, sb + SM_W1A_HI, sb + SM_W1A_LO, wrow, lane);
        gemm_panel(c, sb + SM_A1C_HI, sb + SM_A1C_LO, sb + SM_W1B_HI, sb + SM_W1B_LO, wrow, lane);

        // ---- epi1: m1 = silu(C + rad*w1r + b1) -> A2 panels ----
        #pragma unroll
        for (int mt = 0; mt < 2; mt++) {
            int rowA = wrow + mt * 16 + qr;
            int rowB = rowA + 8;
            float radA = sRad[rowA], radB = sRad[rowB];
            #pragma unroll
            for (int nt = 0; nt < 8; nt++) {
                int c0 = nt * 8 + qc;
                float2 e0 = ep1[c0], e1 = ep1[c0 + 1];
                float v0 = silu(c[mt][nt][0] + radA * e0.y + e0.x);
                float v1 = silu(c[mt][nt][1] + radA * e1.y + e1.x);
                float v2 = silu(c[mt][nt][2] + radB * e0.y + e0.x);
                float v3 = silu(c[mt][nt][3] + radB * e1.y + e1.x);
                uint32_t h, l;
                split2(v0, v1, h, l);
                *(uint32_t*)(smem + SM_A2_HI + SWZ((uint32_t)(rowA * 128 + c0 * 2))) = h;
                *(uint32_t*)(smem + SM_A2_LO + SWZ((uint32_t)(rowA * 128 + c0 * 2))) = l;
                split2(v2, v3, h, l);
                *(uint32_t*)(smem + SM_A2_HI + SWZ((uint32_t)(rowB * 128 + c0 * 2))) = h;
                *(uint32_t*)(smem + SM_A2_LO + SWZ((uint32_t)(rowB * 128 + c0 * 2))) = l;
            }
        }
        __syncwarp();

        // ---- GEMM2: m1 @ W2 ----
        #pragma unroll
        for (int mt = 0; mt < 2; mt++)
            #pragma unroll
            for (int nt = 0; nt < 8; nt++)
                #pragma unroll
                for (int q = 0; q < 4; q++) c[mt][nt][q] = 0.0f;
        gemm_panel(c, sb + SM_A2_HI, sb + SM_A2_LO, sb + SM_W2_HI, sb + SM_W2_LO, wrow, lane);
        __syncwarp();   // all lanes done reading A2 before overwrite

        // ---- epi2: m = silu(C + b2); atomics into g_agg; restage A2 ----
        #pragma unroll
        for (int mt = 0; mt < 2; mt++) {
            int rowA = wrow + mt * 16 + qr;
            int rowB = rowA + 8;
            float* aggA = g_agg + sRidx[rowA] * 64;
            float* aggB = g_agg + sRidx[rowB] * 64;
            #pragma unroll
            for (int nt = 0; nt < 8; nt++) {
                int c0 = nt * 8 + qc;
                float b0 = b2f[c0], b1 = b2f[c0 + 1];
                float v0 = silu(c[mt][nt][0] + b0);
                float v1 = silu(c[mt][nt][1] + b1);
                float v2 = silu(c[mt][nt][2] + b0);
                float v3 = silu(c[mt][nt][3] + b1);
                atomicAdd(&aggA[c0], v0);
                atomicAdd(&aggA[c0 + 1], v1);
                atomicAdd(&aggB[c0], v2);
                atomicAdd(&aggB[c0 + 1], v3);
                uint32_t h, l;
                split2(v0, v1, h, l);
                *(uint32_t*)(smem + SM_A2_HI + SWZ((uint32_t)(rowA * 128 + c0 * 2))) = h;
                *(uint32_t*)(smem + SM_A2_LO + SWZ((uint32_t)(rowA * 128 + c0 * 2))) = l;
                split2(v2, v3, h, l);
                *(uint32_t*)(smem + SM_A2_HI + SWZ((uint32_t)(rowB * 128 + c0 * 2))) = h;
                *(uint32_t*)(smem + SM_A2_LO + SWZ((uint32_t)(rowB * 128 + c0 * 2))) = l;
            }
        }
        __syncwarp();

        // ---- GEMM3: m @ CW1 ----
        #pragma unroll
        for (int mt = 0; mt < 2; mt++)
            #pragma unroll
            for (int nt = 0; nt < 8; nt++)
                #pragma unroll
                for (int q = 0; q < 4; q++) c[mt][nt][q] = 0.0f;
        gemm_panel(c, sb + SM_A2_HI, sb + SM_A2_LO, sb + SM_CW1_HI, sb + SM_CW1_LO, wrow, lane);

        // ---- epi3: sc = silu(C + cb1).cw2 per row; coord atomics ----
        #pragma unroll
        for (int mt = 0; mt < 2; mt++) {
            float pA = 0.0f, pB = 0.0f;
            #pragma unroll
            for (int nt = 0; nt < 8; nt++) {
                int c0 = nt * 8 + qc;
                float2 e0 = ep3[c0], e1 = ep3[c0 + 1];
                pA += silu(c[mt][nt][0] + e0.x) * e0.y + silu(c[mt][nt][1] + e1.x) * e1.y;
                pB += silu(c[mt][nt][2] + e0.x) * e0.y + silu(c[mt][nt][3] + e1.x) * e1.y;
            }
            pA += __shfl_xor_sync(0xFFFFFFFFu, pA, 1);
            pA += __shfl_xor_sync(0xFFFFFFFFu, pA, 2);
            pB += __shfl_xor_sync(0xFFFFFFFFu, pB, 1);
            pB += __shfl_xor_sync(0xFFFFFFFFu, pB, 2);
            if ((lane & 3) == 0) {
                int rowA = wrow + mt * 16 + qr;
                int rowB = rowA + 8;
                int rA = sRidx[rowA], rB = sRidx[rowB];
                atomicAdd(&g_cagg[rA * 3 + 0], sDiff[rowA * 3 + 0] * pA);
                atomicAdd(&g_cagg[rA * 3 + 1], sDiff[rowA * 3 + 1] * pA);
                atomicAdd(&g_cagg[rA * 3 + 2], sDiff[rowA * 3 + 2] * pA);
                atomicAdd(&g_cagg[rB * 3 + 0], sDiff[rowB * 3 + 0] * pB);
                atomicAdd(&g_cagg[rB * 3 + 1], sDiff[rowB * 3 + 1] * pB);
                atomicAdd(&g_cagg[rB * 3 + 2], sDiff[rowB * 3 + 2] * pB);
            }
        }
        __syncthreads();   // before next tile's gather overwrites A1/meta
    }
}

// ================= node kernel (fp32 pair-packed, from R3) =====================
#define EPW 8
#define CTA_THREADS 512
#define WARPS_CTA 16
#define TILE_E (EPW * WARPS_CTA)
#define NODE_TILES ((N_NODES + TILE_E - 1) / TILE_E)
#define GRID_PERSIST 152

typedef unsigned long long ull;
union F2u { ull u; float2 f; };

__device__ __forceinline__ ull splat2(float v) {
    ull r; asm("mov.b64 %0, {%1, %1};" : "=l"(r) : "f"(v)); return r;
}
__device__ __forceinline__ void ffma2(ull& a, ull x, ull y) {
    asm("fma.rn.f32x2 %0, %1, %2, %0;" : "+l"(a) : "l"(x), "l"(y));
}

template<int K, int STRIDE>
__device__ __forceinline__ void gemm_pair(ull acc[4][2], const float* __restrict__ W,
                                          const float* __restrict__ fp, int lane) {
    #pragma unroll 4
    for (int k = 0; k < K; k += 2) {
        float2 w0 = ((const float2*)(W + k * 64))[lane];
        float2 w1 = ((const float2*)(W + (k + 1) * 64))[lane];
        ull w00 = splat2(w0.x), w01 = splat2(w0.y);
        ull w10 = splat2(w1.x), w11 = splat2(w1.y);
        #pragma unroll
        for (int p = 0; p < 4; p++) {
            ulonglong2 f = *(const ulonglong2*)(fp + p * STRIDE + 2 * k);
            ffma2(acc[p][0], f.x, w00);
            ffma2(acc[p][1], f.x, w01);
            ffma2(acc[p][0], f.y, w10);
            ffma2(acc[p][1], f.y, w11);
        }
    }
}

#define NPS 260
#define UPS 132
#define N_OFF_W1   0
#define N_OFF_W2   8192
#define N_OFF_B1   12288
#define N_OFF_B2   12352
#define N_OFF_FEAT 12416
#define N_OFF_U    (N_OFF_FEAT + WARPS_CTA * 4 * NPS)
#define N_SMEM_FLOATS (N_OFF_U + WARPS_CTA * 4 * UPS)

__global__ __launch_bounds__(CTA_THREADS, 1) void node_kernel(
    const float* __restrict__ W1, const float* __restrict__ B1,
    const float* __restrict__ W2, const float* __restrict__ B2)
{
    extern __shared__ float s[];
    float* sW1 = s + N_OFF_W1;
    float* sW2 = s + N_OFF_W2;
    float* sB1 = s + N_OFF_B1;
    float* sB2 = s + N_OFF_B2;

    int tid = threadIdx.x;
    for (int i = tid; i < 8192; i += CTA_THREADS) sW1[i] = W1[i];
    for (int i = tid; i < 4096; i += CTA_THREADS) sW2[i] = W2[i];
    if (tid < 64) { sB1[tid] = B1[tid]; sB2[tid] = B2[tid]; }
    __syncthreads();

    int lane = tid & 31;
    int wid  = tid >> 5;
    float* fw = s + N_OFF_FEAT + wid * (4 * NPS);
    float* uw = s + N_OFF_U    + wid * (4 * UPS);

    float2 b1v = ((const float2*)sB1)[lane];
    float2 b2v = ((const float2*)sB2)[lane];

    for (int tile = blockIdx.x; tile < NODE_TILES; tile += gridDim.x) {
        int nbase = tile * TILE_E + wid * EPW;

        #pragma unroll
        for (int e = 0; e < EPW; e++) {
            int n = nbase + e;
            if (n < N_NODES) {
                float* fpq = fw + (e >> 1) * NPS + (e & 1);
                fpq[2 * lane]       = g_h[n * HID + lane];
                fpq[64 + 2 * lane]  = g_h[n * HID + 32 + lane];
                fpq[128 + 2 * lane] = g_agg[n * HID + lane];
                fpq[192 + 2 * lane] = g_agg[n * HID + 32 + lane];
            }
        }
        __syncwarp();

        ull acc[4][2];
        #pragma unroll
        for (int p = 0; p < 4; p++) { acc[p][0] = splat2(b1v.x); acc[p][1] = splat2(b1v.y); }
        gemm_pair<128, NPS>(acc, sW1, fw, lane);
        #pragma unroll
        for (int p = 0; p < 4; p++) {
            F2u a0, a1; a0.u = acc[p][0]; a1.u = acc[p][1];
            a0.f.x = silu(a0.f.x); a0.f.y = silu(a0.f.y);
            a1.f.x = silu(a1.f.x); a1.f.y = silu(a1.f.y);
            *(ulonglong2*)(uw + p * UPS + 4 * lane) = make_ulonglong2(a0.u, a1.u);
        }
        __syncwarp();

        #pragma unroll
        for (int p = 0; p < 4; p++) { acc[p][0] = splat2(b2v.x); acc[p][1] = splat2(b2v.y); }
        gemm_pair<64, UPS>(acc, sW2, uw, lane);

        #pragma unroll
        for (int p = 0; p < 4; p++) {
            F2u a0, a1; a0.u = acc[p][0]; a1.u = acc[p][1];
            float4 hq = *(const float4*)(fw + p * NPS + 4 * lane);
            int n0 = nbase + 2 * p, n1 = n0 + 1;
            if (n0 < N_NODES) {
                ((float2*)(g_h + n0 * HID))[lane] =
                    make_float2(hq.x + a0.f.x, hq.z + a1.f.x);
                if (lane < 3) {
                    float cnt = g_cnt[n0];
                    if (cnt < 1.0f) cnt = 1.0f;
                    g_x[n0 * 3 + lane] += g_cagg[n0 * 3 + lane] / cnt;
                }
            }
            if (n1 < N_NODES) {
                ((float2*)(g_h + n1 * HID))[lane] =
                    make_float2(hq.y + a0.f.y, hq.w + a1.f.y);
                if (lane < 3) {
                    float cnt = g_cnt[n1];
                    if (cnt < 1.0f) cnt = 1.0f;
                    g_x[n1 * 3 + lane] += g_cagg[n1 * 3 + lane] / cnt;
                }
            }
        }
        __syncwarp();
    }
}

// ---------------- head ---------------------------------------------------------
#define H_OFF_EW   0
#define H_OFF_HW1  4096
#define H_OFF_HW2  8192
#define H_OFF_EB   9472
#define H_OFF_HB1  9536
#define H_OFF_HB2  9600
#define H_OFF_FEAT 9620
#define H_SMEM_FLOATS 10132

__global__ __launch_bounds__(256) void head_kernel(
    const float* __restrict__ EW, const float* __restrict__ EB,
    const float* __restrict__ HW1, const float* __restrict__ HB1,
    const float* __restrict__ HW2, const float* __restrict__ HB2,
    float* __restrict__ out)
{
    extern __shared__ float s[];
    float* sEW  = s + H_OFF_EW;
    float* sHW1 = s + H_OFF_HW1;
    float* sHW2 = s + H_OFF_HW2;
    float* sEB  = s + H_OFF_EB;
    float* sHB1 = s + H_OFF_HB1;
    float* sHB2 = s + H_OFF_HB2;

    int tid = threadIdx.x;
    for (int i = tid; i < 4096; i += 256) { sEW[i] = EW[i]; sHW1[i] = HW1[i]; }
    for (int i = tid; i < 1280; i += 256) sHW2[i] = HW2[i];
    if (tid < 64) { sEB[tid] = EB[tid]; sHB1[tid] = HB1[tid]; }
    if (tid < 20) sHB2[tid] = HB2[tid];
    __syncthreads();

    int lane = tid & 31;
    int wloc = tid >> 5;
    float* fw = s + H_OFF_FEAT + wloc * 64;

    int warp   = (blockIdx.x * blockDim.x + tid) >> 5;
    int nwarps = (gridDim.x * blockDim.x) >> 5;

    for (int n = warp; n < N_NODES; n += nwarps) {
        float h0 = g_h[n * HID + lane], h1 = g_h[n * HID + 32 + lane];
        fw[lane] = h0; fw[32 + lane] = h1;
        __syncwarp();

        float t0 = sEB[lane], t1 = sEB[32 + lane];
        #pragma unroll 8
        for (int k = 0; k < 64; k++) {
            float f = fw[k];
            t0 = fmaf(f, sEW[k * 64 + lane], t0);
            t1 = fmaf(f, sEW[k * 64 + 32 + lane], t1);
        }
        __syncwarp();
        fw[lane] = t0; fw[32 + lane] = t1;
        __syncwarp();

        float r0 = sHB1[lane], r1 = sHB1[32 + lane];
        #pragma unroll 8
        for (int k = 0; k < 64; k++) {
            float f = fw[k];
            r0 = fmaf(f, sHW1[k * 64 + lane], r0);
            r1 = fmaf(f, sHW1[k * 64 + 32 + lane], r1);
        }
        r0 = fmaxf(r0, 0.0f); r1 = fmaxf(r1, 0.0f);
        __syncwarp();
        fw[lane] = r0; fw[32 + lane] = r1;
        __syncwarp();

        if (lane < OUT_NF) {
            float o = sHB2[lane];
            #pragma unroll 8
            for (int k = 0; k < 64; k++)
                o = fmaf(fw[k], sHW2[k * OUT_NF + lane], o);
            out[n * OUT_NF + lane] = o;
        }
        __syncwarp();
    }
}

// ---------------- launcher ----------------------------------------------------
extern "C" void kernel_launch(void* const* d_in, const int* in_sizes, int n_in,
                              void* d_out, int out_size) {
    const float* h_in      = (const float*)d_in[0];
    const float* x_in      = (const float*)d_in[1];
    const int*   edges     = (const int*)d_in[2];
    const float* emb_in_w  = (const float*)d_in[3];
    const float* emb_in_b  = (const float*)d_in[4];
    const float* emb_out_w = (const float*)d_in[5];
    const float* emb_out_b = (const float*)d_in[6];
    const float* edge_w1   = (const float*)d_in[7];
    const float* edge_b1   = (const float*)d_in[8];
    const float* edge_w2   = (const float*)d_in[9];
    const float* edge_b2   = (const float*)d_in[10];
    const float* node_w1   = (const float*)d_in[11];
    const float* node_b1   = (const float*)d_in[12];
    const float* node_w2   = (const float*)d_in[13];
    const float* node_b2   = (const float*)d_in[14];
    const float* coord_w1  = (const float*)d_in[15];
    const float* coord_b1  = (const float*)d_in[16];
    const float* coord_w2  = (const float*)d_in[17];
    const float* head_w1   = (const float*)d_in[18];
    const float* head_b1   = (const float*)d_in[19];
    const float* head_w2   = (const float*)d_in[20];
    const float* head_b2   = (const float*)d_in[21];
    float* out = (float*)d_out;

    cudaFuncSetAttribute(edge_mma_kernel, cudaFuncAttributeMaxDynamicSharedMemorySize,
                         SM_TOTAL_E);
    cudaFuncSetAttribute(node_kernel, cudaFuncAttributeMaxDynamicSharedMemorySize,
                         N_SMEM_FLOATS * sizeof(float));
    cudaFuncSetAttribute(head_kernel, cudaFuncAttributeMaxDynamicSharedMemorySize,
                         H_SMEM_FLOATS * sizeof(float));

    const int* row = edges;
    const int* col = edges + N_EDGES;

    init_kernel<<<(N_NODES * 3 + 255) / 256, 256>>>(x_in);
    embed_kernel<<<(N_NODES * HID + 255) / 256, 256>>>(h_in, emb_in_w, emb_in_b);
    count_kernel<<<(N_EDGES + 255) / 256, 256>>>(row);

    for (int l = 0; l < N_LAYERS; l++) {
        zero_kernel<<<2048, 256>>>();
        edge_mma_kernel<<<EK_GRID, EK_THREADS, SM_TOTAL_E>>>(
            row, col,
            edge_w1 + l * (2 * HID + 1) * HID, edge_b1 + l * HID,
            edge_w2 + l * HID * HID, edge_b2 + l * HID,
            coord_w1 + l * HID * HID, coord_b1 + l * HID,
            coord_w2 + l * HID);
        node_kernel<<<GRID_PERSIST, CTA_THREADS, N_SMEM_FLOATS * sizeof(float)>>>(
            node_w1 + l * 2 * HID * HID, node_b1 + l * HID,
            node_w2 + l * HID * HID, node_b2 + l * HID);
    }

    head_kernel<<<6250, 256, H_SMEM_FLOATS * sizeof(float)>>>(
        emb_out_w, emb_out_b, head_w1, head_b1, head_w2, head_b2, out);
}

// round 10
// speedup vs baseline: 1.5398x; 1.5398x over previous
#include <cuda_runtime.h>
#include <cuda_bf16.h>
#include <cstdint>

#define N_NODES 50000
#define N_EDGES 800000
#define IN_NF 21
#define HID 64
#define OUT_NF 20
#define N_LAYERS 4

// ---------------- scratch (device globals; no runtime allocation) -------------
__device__ float g_h[N_NODES * HID];
__device__ float g_x[N_NODES * 3];
__device__ float g_cnt[N_NODES];
__device__ float g_agg[N_NODES * HID];
__device__ float g_cagg[N_NODES * 3];

__device__ __forceinline__ float silu(float v) {
    return v / (1.0f + __expf(-v));
}

#define SWZ(off) ((off) ^ (((off) >> 3) & 0x70))

__device__ __forceinline__ uint32_t smem_u32(const void* p) {
    uint32_t a;
    asm("{ .reg .u64 t; cvta.to.shared.u64 t, %1; cvt.u32.u64 %0, t; }"
        : "=r"(a) : "l"(p));
    return a;
}

// pack two fp32 -> bf16x2 (v0 -> low 16 bits)
__device__ __forceinline__ uint32_t bf16x2_pack(float v0, float v1) {
    uint32_t r;
    asm("cvt.rn.bf16x2.f32 %0, %1, %2;" : "=r"(r) : "f"(v1), "f"(v0));
    return r;
}
__device__ __forceinline__ void split2(float v0, float v1, uint32_t& h, uint32_t& l) {
    h = bf16x2_pack(v0, v1);
    float h0 = __uint_as_float(h << 16);
    float h1 = __uint_as_float(h & 0xFFFF0000u);
    l = bf16x2_pack(v0 - h0, v1 - h1);
}

__device__ __forceinline__ void ldsm4(uint32_t addr, uint32_t r[4]) {
    asm volatile("ldmatrix.sync.aligned.m8n8.x4.shared.b16 {%0,%1,%2,%3}, [%4];"
        : "=r"(r[0]), "=r"(r[1]), "=r"(r[2]), "=r"(r[3]) : "r"(addr));
}
__device__ __forceinline__ void mma16816(float* c, const uint32_t* a, const uint32_t* b) {
    asm volatile(
        "mma.sync.aligned.m16n8k16.row.col.f32.bf16.bf16.f32 "
        "{%0,%1,%2,%3}, {%4,%5,%6,%7}, {%8,%9}, {%0,%1,%2,%3};"
        : "+f"(c[0]), "+f"(c[1]), "+f"(c[2]), "+f"(c[3])
        : "r"(a[0]), "r"(a[1]), "r"(a[2]), "r"(a[3]), "r"(b[0]), "r"(b[1]));
}

// ---------------- small kernels ------------------------------------------------
__global__ void init_kernel(const float* __restrict__ x_in) {
    int stride = gridDim.x * blockDim.x;
    int t0 = blockIdx.x * blockDim.x + threadIdx.x;
    for (int i = t0; i < N_NODES * HID; i += stride) g_agg[i] = 0.0f;
    for (int i = t0; i < N_NODES * 3; i += stride) { g_x[i] = x_in[i]; g_cagg[i] = 0.0f; }
    for (int i = t0; i < N_NODES; i += stride) g_cnt[i] = 0.0f;
}

__global__ void embed_kernel(const float* __restrict__ h_in,
                             const float* __restrict__ W,
                             const float* __restrict__ b) {
    int i = blockIdx.x * blockDim.x + threadIdx.x;
    if (i >= N_NODES * HID) return;
    int n = i >> 6;
    int c = i & 63;
    const float* hr = h_in + n * IN_NF;
    float acc = b[c];
    #pragma unroll
    for (int k = 0; k < IN_NF; k++) acc = fmaf(hr[k], W[k * HID + c], acc);
    g_h[i] = acc;
}

__global__ void count_kernel(const int* __restrict__ row) {
    int e = blockIdx.x * blockDim.x + threadIdx.x;
    if (e < N_EDGES) atomicAdd(&g_cnt[row[e]], 1.0f);
}

// ================= edge kernel: mma.sync bf16, 128-edge tiles ==================
// smem byte offsets; all panels [rows][64] bf16, 128B/row, SW128 swizzled.
#define SM_W1A_HI  0
#define SM_W1A_LO  8192
#define SM_W1B_HI  16384
#define SM_W1B_LO  24576
#define SM_W2_HI   32768
#define SM_W2_LO   40960
#define SM_CW1_HI  49152
#define SM_CW1_LO  57344
#define SM_A1R_HI  65536
#define SM_A1R_LO  81920
#define SM_A1C_HI  98304
#define SM_A1C_LO  114688
#define SM_A2_HI   131072
#define SM_A2_LO   147456
#define SM_EP1     163840
#define SM_B2F     164352
#define SM_EP3     164608
#define SM_RAD     165120
#define SM_RIDX    165632
#define SM_DIFF    166144
#define SM_TOTAL_E 167680

#define EK_THREADS 256
#define E_TILES (N_EDGES / 128)   // 6250 exact
#define EK_GRID 152

// 3-pass split-bf16 GEMM over one K=64 panel: C += A*B^T (+ AhBl + AlBh)
// A panel: [128 rows][64 k]; B panel: [64 n][64 k]. Warp handles the 16 rows
// [mBase, mBase+16). c[nt][4] fragments.
__device__ __forceinline__ void gemm_panel(float c[8][4],
                                           uint32_t aHi, uint32_t aLo,
                                           uint32_t bHi, uint32_t bLo,
                                           int mBase, int lane) {
    int g = lane >> 3, r = lane & 7;
    int aRow  = mBase + ((g & 1) << 3) + r;
    int aKoff = (g >> 1) << 4;                  // 0 / 16 bytes
    int bRow  = ((g >> 1) << 3) + r;            // + nt2*16
    int bKoff = (g & 1) << 4;
    #pragma unroll
    for (int kt = 0; kt < 4; kt++) {
        int kb = kt << 5;                       // 32 bytes per k16
        #pragma unroll
        for (int combo = 0; combo < 3; combo++) {
            uint32_t aOff = (combo == 2) ? aLo : aHi;
            uint32_t bOff = (combo == 1) ? bLo : bHi;
            uint32_t a0[4], b[4][4];
            ldsm4(aOff + SWZ((uint32_t)(aRow * 128 + kb + aKoff)), a0);
            #pragma unroll
            for (int nt2 = 0; nt2 < 4; nt2++)
                ldsm4(bOff + SWZ((uint32_t)((bRow + nt2 * 16) * 128 + kb + bKoff)), b[nt2]);
            #pragma unroll
            for (int nt2 = 0; nt2 < 4; nt2++) {
                mma16816(c[2 * nt2],     a0, &b[nt2][0]);
                mma16816(c[2 * nt2 + 1], a0, &b[nt2][2]);
            }
        }
    }
}

__global__ __launch_bounds__(EK_THREADS, 1) void edge_mma_kernel(
    const int* __restrict__ row, const int* __restrict__ col,
    const float* __restrict__ W1, const float* __restrict__ B1,
    const float* __restrict__ W2, const float* __restrict__ B2,
    const float* __restrict__ CW1, const float* __restrict__ CB1,
    const float* __restrict__ CW2)
{
    extern __shared__ char smem[];
    uint32_t sb = smem_u32(smem);
    int tid   = threadIdx.x;
    int lane  = tid & 31;
    int wid   = tid >> 5;
    int wrow  = wid * 16;          // 16 rows per warp, 8 warps = 128 rows

    // ---- stage weights transposed + split: panels [n][k] bf16, SW128 ----
    for (int idx = tid; idx < 8192; idx += EK_THREADS) {
        int k = idx >> 6, n = idx & 63;
        float v = W1[k * 64 + n];
        __nv_bfloat16 hb = __float2bfloat16(v);
        __nv_bfloat16 lb = __float2bfloat16(v - __bfloat162float(hb));
        uint32_t off = SWZ((uint32_t)(n * 128 + (k & 63) * 2));
        int bhi = (k < 64) ? SM_W1A_HI : SM_W1B_HI;
        int blo = (k < 64) ? SM_W1A_LO : SM_W1B_LO;
        *(__nv_bfloat16*)(smem + bhi + off) = hb;
        *(__nv_bfloat16*)(smem + blo + off) = lb;
    }
    for (int idx = tid; idx < 4096; idx += EK_THREADS) {
        int k = idx >> 6, n = idx & 63;
        uint32_t off = SWZ((uint32_t)(n * 128 + k * 2));
        {
            float v = W2[k * 64 + n];
            __nv_bfloat16 hb = __float2bfloat16(v);
            __nv_bfloat16 lb = __float2bfloat16(v - __bfloat162float(hb));
            *(__nv_bfloat16*)(smem + SM_W2_HI + off) = hb;
            *(__nv_bfloat16*)(smem + SM_W2_LO + off) = lb;
        }
        {
            float v = CW1[k * 64 + n];
            __nv_bfloat16 hb = __float2bfloat16(v);
            __nv_bfloat16 lb = __float2bfloat16(v - __bfloat162float(hb));
            *(__nv_bfloat16*)(smem + SM_CW1_HI + off) = hb;
            *(__nv_bfloat16*)(smem + SM_CW1_LO + off) = lb;
        }
    }
    if (tid < 64) {
        ((float2*)(smem + SM_EP1))[tid] = make_float2(B1[tid], W1[128 * 64 + tid]);
        ((float*)(smem + SM_B2F))[tid]  = B2[tid];
        ((float2*)(smem + SM_EP3))[tid] = make_float2(CB1[tid], CW2[tid]);
    }
    __syncthreads();

    const float2* ep1  = (const float2*)(smem + SM_EP1);
    const float*  b2f  = (const float*)(smem + SM_B2F);
    const float2* ep3  = (const float2*)(smem + SM_EP3);
    float* sRad  = (float*)(smem + SM_RAD);
    int*   sRidx = (int*)(smem + SM_RIDX);
    float* sDiff = (float*)(smem + SM_DIFF);

    int qr = lane >> 2;          // 0..7
    int qc = (lane & 3) << 1;    // col base within n8

    int erow = tid >> 1;         // two threads per edge row
    int half = tid & 1;

    // NOTE: all staging rows [wrow, wrow+16) are written by threads
    // [2*wrow, 2*wrow+32) = this warp, and read only by this warp:
    // warps are fully independent; only __syncwarp needed inside the loop.
    for (int tile = blockIdx.x; tile < E_TILES; tile += gridDim.x) {
        // ---- gather: 2 threads per edge ----
        {
            int e  = tile * 128 + erow;
            int rr = __ldg(&row[e]);
            int cc = __ldg(&col[e]);
            if (half == 0) {
                float d0 = __ldg(&g_x[rr * 3 + 0]) - __ldg(&g_x[cc * 3 + 0]);
                float d1 = __ldg(&g_x[rr * 3 + 1]) - __ldg(&g_x[cc * 3 + 1]);
                float d2 = __ldg(&g_x[rr * 3 + 2]) - __ldg(&g_x[cc * 3 + 2]);
                sRad[erow]  = d0 * d0 + d1 * d1 + d2 * d2;
                sRidx[erow] = rr;
                sDiff[erow * 3 + 0] = d0;
                sDiff[erow * 3 + 1] = d1;
                sDiff[erow * 3 + 2] = d2;
            }
            const float4* hr4 = (const float4*)(g_h + rr * 64);
            const float4* hc4 = (const float4*)(g_h + cc * 64);
            #pragma unroll
            for (int j = 0; j < 4; j++) {
                int jj = half * 4 + j;
                uint32_t off = SWZ((uint32_t)(erow * 128 + jj * 16));
                float4 f0 = __ldg(&hr4[2 * jj]);
                float4 f1 = __ldg(&hr4[2 * jj + 1]);
                uint32_t h0, h1, h2, h3, l0, l1, l2, l3;
                split2(f0.x, f0.y, h0, l0); split2(f0.z, f0.w, h1, l1);
                split2(f1.x, f1.y, h2, l2); split2(f1.z, f1.w, h3, l3);
                *(uint4*)(smem + SM_A1R_HI + off) = make_uint4(h0, h1, h2, h3);
                *(uint4*)(smem + SM_A1R_LO + off) = make_uint4(l0, l1, l2, l3);
                f0 = __ldg(&hc4[2 * jj]);
                f1 = __ldg(&hc4[2 * jj + 1]);
                split2(f0.x, f0.y, h0, l0); split2(f0.z, f0.w, h1, l1);
                split2(f1.x, f1.y, h2, l2); split2(f1.z, f1.w, h3, l3);
                *(uint4*)(smem + SM_A1C_HI + off) = make_uint4(h0, h1, h2, h3);
                *(uint4*)(smem + SM_A1C_LO + off) = make_uint4(l0, l1, l2, l3);
            }
        }
        __syncwarp();

        float c[8][4];

        // ---- GEMM1: feat @ W1 (two K=64 panels) ----
        #pragma unroll
        for (int nt = 0; nt < 8; nt++)
            #pragma unroll
            for (int q = 0; q < 4; q++) c[nt][q] = 0.0f;
        gemm_panel(c, sb + SM_A1R_HI, sb + SM_A1R_LO, sb + SM_W1A_HI, sb + SM_W1A_LO, wrow, lane);
        gemm_panel(c, sb + SM_A1C_HI, sb + SM_A1C_LO, sb + SM_W1B_HI, sb + SM_W1B_LO, wrow, lane);

        // ---- epi1: m1 = silu(C + rad*w1r + b1) -> A2 panel ----
        {
            int rowA = wrow + qr;
            int rowB = rowA + 8;
            float radA = sRad[rowA], radB = sRad[rowB];
            #pragma unroll
            for (int nt = 0; nt < 8; nt++) {
                int c0 = nt * 8 + qc;
                float2 e0 = ep1[c0], e1 = ep1[c0 + 1];
                float v0 = silu(c[nt][0] + radA * e0.y + e0.x);
                float v1 = silu(c[nt][1] + radA * e1.y + e1.x);
                float v2 = silu(c[nt][2] + radB * e0.y + e0.x);
                float v3 = silu(c[nt][3] + radB * e1.y + e1.x);
                uint32_t h, l;
                split2(v0, v1, h, l);
                *(uint32_t*)(smem + SM_A2_HI + SWZ((uint32_t)(rowA * 128 + c0 * 2))) = h;
                *(uint32_t*)(smem + SM_A2_LO + SWZ((uint32_t)(rowA * 128 + c0 * 2))) = l;
                split2(v2, v3, h, l);
                *(uint32_t*)(smem + SM_A2_HI + SWZ((uint32_t)(rowB * 128 + c0 * 2))) = h;
                *(uint32_t*)(smem + SM_A2_LO + SWZ((uint32_t)(rowB * 128 + c0 * 2))) = l;
            }
        }
        __syncwarp();

        // ---- GEMM2: m1 @ W2 ----
        #pragma unroll
        for (int nt = 0; nt < 8; nt++)
            #pragma unroll
            for (int q = 0; q < 4; q++) c[nt][q] = 0.0f;
        gemm_panel(c, sb + SM_A2_HI, sb + SM_A2_LO, sb + SM_W2_HI, sb + SM_W2_LO, wrow, lane);
        __syncwarp();   // all lanes done reading A2 before overwrite

        // ---- epi2: m = silu(C + b2); atomics into g_agg; restage A2 ----
        {
            int rowA = wrow + qr;
            int rowB = rowA + 8;
            float* aggA = g_agg + sRidx[rowA] * 64;
            float* aggB = g_agg + sRidx[rowB] * 64;
            #pragma unroll
            for (int nt = 0; nt < 8; nt++) {
                int c0 = nt * 8 + qc;
                float b0 = b2f[c0], b1 = b2f[c0 + 1];
                float v0 = silu(c[nt][0] + b0);
                float v1 = silu(c[nt][1] + b1);
                float v2 = silu(c[nt][2] + b0);
                float v3 = silu(c[nt][3] + b1);
                atomicAdd(&aggA[c0], v0);
                atomicAdd(&aggA[c0 + 1], v1);
                atomicAdd(&aggB[c0], v2);
                atomicAdd(&aggB[c0 + 1], v3);
                uint32_t h, l;
                split2(v0, v1, h, l);
                *(uint32_t*)(smem + SM_A2_HI + SWZ((uint32_t)(rowA * 128 + c0 * 2))) = h;
                *(uint32_t*)(smem + SM_A2_LO + SWZ((uint32_t)(rowA * 128 + c0 * 2))) = l;
                split2(v2, v3, h, l);
                *(uint32_t*)(smem + SM_A2_HI + SWZ((uint32_t)(rowB * 128 + c0 * 2))) = h;
                *(uint32_t*)(smem + SM_A2_LO + SWZ((uint32_t)(rowB * 128 + c0 * 2))) = l;
            }
        }
        __syncwarp();

        // ---- GEMM3: m @ CW1 ----
        #pragma unroll
        for (int nt = 0; nt < 8; nt++)
            #pragma unroll
            for (int q = 0; q < 4; q++) c[nt][q] = 0.0f;
        gemm_panel(c, sb + SM_A2_HI, sb + SM_A2_LO, sb + SM_CW1_HI, sb + SM_CW1_LO, wrow, lane);

        // ---- epi3: sc = silu(C + cb1).cw2 per row; coord atomics ----
        {
            float pA = 0.0f, pB = 0.0f;
            #pragma unroll
            for (int nt = 0; nt < 8; nt++) {
                int c0 = nt * 8 + qc;
                float2 e0 = ep3[c0], e1 = ep3[c0 + 1];
                pA += silu(c[nt][0] + e0.x) * e0.y + silu(c[nt][1] + e1.x) * e1.y;
                pB += silu(c[nt][2] + e0.x) * e0.y + silu(c[nt][3] + e1.x) * e1.y;
            }
            pA += __shfl_xor_sync(0xFFFFFFFFu, pA, 1);
            pA += __shfl_xor_sync(0xFFFFFFFFu, pA, 2);
            pB += __shfl_xor_sync(0xFFFFFFFFu, pB, 1);
            pB += __shfl_xor_sync(0xFFFFFFFFu, pB, 2);
            if ((lane & 3) == 0) {
                int rowA = wrow + qr;
                int rowB = rowA + 8;
                int rA = sRidx[rowA], rB = sRidx[rowB];
                atomicAdd(&g_cagg[rA * 3 + 0], sDiff[rowA * 3 + 0] * pA);
                atomicAdd(&g_cagg[rA * 3 + 1], sDiff[rowA * 3 + 1] * pA);
                atomicAdd(&g_cagg[rA * 3 + 2], sDiff[rowA * 3 + 2] * pA);
                atomicAdd(&g_cagg[rB * 3 + 0], sDiff[rowB * 3 + 0] * pB);
                atomicAdd(&g_cagg[rB * 3 + 1], sDiff[rowB * 3 + 1] * pB);
                atomicAdd(&g_cagg[rB * 3 + 2], sDiff[rowB * 3 + 2] * pB);
            }
        }
        __syncwarp();   // before next tile's gather overwrites A1/meta
    }
}

// ================= node kernel (fp32 pair-packed; zeroes agg after use) ========
#define EPW 8
#define CTA_THREADS 512
#define WARPS_CTA 16
#define TILE_E (EPW * WARPS_CTA)
#define NODE_TILES ((N_NODES + TILE_E - 1) / TILE_E)
#define GRID_PERSIST 152

typedef unsigned long long ull;
union F2u { ull u; float2 f; };

__device__ __forceinline__ ull splat2(float v) {
    ull r; asm("mov.b64 %0, {%1, %1};" : "=l"(r) : "f"(v)); return r;
}
__device__ __forceinline__ void ffma2(ull& a, ull x, ull y) {
    asm("fma.rn.f32x2 %0, %1, %2, %0;" : "+l"(a) : "l"(x), "l"(y));
}

template<int K, int STRIDE>
__device__ __forceinline__ void gemm_pair(ull acc[4][2], const float* __restrict__ W,
                                          const float* __restrict__ fp, int lane) {
    #pragma unroll 4
    for (int k = 0; k < K; k += 2) {
        float2 w0 = ((const float2*)(W + k * 64))[lane];
        float2 w1 = ((const float2*)(W + (k + 1) * 64))[lane];
        ull w00 = splat2(w0.x), w01 = splat2(w0.y);
        ull w10 = splat2(w1.x), w11 = splat2(w1.y);
        #pragma unroll
        for (int p = 0; p < 4; p++) {
            ulonglong2 f = *(const ulonglong2*)(fp + p * STRIDE + 2 * k);
            ffma2(acc[p][0], f.x, w00);
            ffma2(acc[p][1], f.x, w01);
            ffma2(acc[p][0], f.y, w10);
            ffma2(acc[p][1], f.y, w11);
        }
    }
}

#define NPS 260
#define UPS 132
#define N_OFF_W1   0
#define N_OFF_W2   8192
#define N_OFF_B1   12288
#define N_OFF_B2   12352
#define N_OFF_FEAT 12416
#define N_OFF_U    (N_OFF_FEAT + WARPS_CTA * 4 * NPS)
#define N_SMEM_FLOATS (N_OFF_U + WARPS_CTA * 4 * UPS)

__global__ __launch_bounds__(CTA_THREADS, 1) void node_kernel(
    const float* __restrict__ W1, const float* __restrict__ B1,
    const float* __restrict__ W2, const float* __restrict__ B2)
{
    extern __shared__ float s[];
    float* sW1 = s + N_OFF_W1;
    float* sW2 = s + N_OFF_W2;
    float* sB1 = s + N_OFF_B1;
    float* sB2 = s + N_OFF_B2;

    int tid = threadIdx.x;
    for (int i = tid; i < 8192; i += CTA_THREADS) sW1[i] = W1[i];
    for (int i = tid; i < 4096; i += CTA_THREADS) sW2[i] = W2[i];
    if (tid < 64) { sB1[tid] = B1[tid]; sB2[tid] = B2[tid]; }
    __syncthreads();

    int lane = tid & 31;
    int wid  = tid >> 5;
    float* fw = s + N_OFF_FEAT + wid * (4 * NPS);
    float* uw = s + N_OFF_U    + wid * (4 * UPS);

    float2 b1v = ((const float2*)sB1)[lane];
    float2 b2v = ((const float2*)sB2)[lane];

    for (int tile = blockIdx.x; tile < NODE_TILES; tile += gridDim.x) {
        int nbase = tile * TILE_E + wid * EPW;

        #pragma unroll
        for (int e = 0; e < EPW; e++) {
            int n = nbase + e;
            if (n < N_NODES) {
                float* fpq = fw + (e >> 1) * NPS + (e & 1);
                fpq[2 * lane]       = g_h[n * HID + lane];
                fpq[64 + 2 * lane]  = g_h[n * HID + 32 + lane];
                fpq[128 + 2 * lane] = g_agg[n * HID + lane];
                fpq[192 + 2 * lane] = g_agg[n * HID + 32 + lane];
                // re-zero aggregation for the next layer's edge pass
                g_agg[n * HID + lane] = 0.0f;
                g_agg[n * HID + 32 + lane] = 0.0f;
            }
        }
        __syncwarp();

        ull acc[4][2];
        #pragma unroll
        for (int p = 0; p < 4; p++) { acc[p][0] = splat2(b1v.x); acc[p][1] = splat2(b1v.y); }
        gemm_pair<128, NPS>(acc, sW1, fw, lane);
        #pragma unroll
        for (int p = 0; p < 4; p++) {
            F2u a0, a1; a0.u = acc[p][0]; a1.u = acc[p][1];
            a0.f.x = silu(a0.f.x); a0.f.y = silu(a0.f.y);
            a1.f.x = silu(a1.f.x); a1.f.y = silu(a1.f.y);
            *(ulonglong2*)(uw + p * UPS + 4 * lane) = make_ulonglong2(a0.u, a1.u);
        }
        __syncwarp();

        #pragma unroll
        for (int p = 0; p < 4; p++) { acc[p][0] = splat2(b2v.x); acc[p][1] = splat2(b2v.y); }
        gemm_pair<64, UPS>(acc, sW2, uw, lane);

        #pragma unroll
        for (int p = 0; p < 4; p++) {
            F2u a0, a1; a0.u = acc[p][0]; a1.u = acc[p][1];
            float4 hq = *(const float4*)(fw + p * NPS + 4 * lane);
            int n0 = nbase + 2 * p, n1 = n0 + 1;
            if (n0 < N_NODES) {
                ((float2*)(g_h + n0 * HID))[lane] =
                    make_float2(hq.x + a0.f.x, hq.z + a1.f.x);
                if (lane < 3) {
                    float cnt = g_cnt[n0];
                    if (cnt < 1.0f) cnt = 1.0f;
                    g_x[n0 * 3 + lane] += g_cagg[n0 * 3 + lane] / cnt;
                    g_cagg[n0 * 3 + lane] = 0.0f;
                }
            }
            if (n1 < N_NODES) {
                ((float2*)(g_h + n1 * HID))[lane] =
                    make_float2(hq.y + a0.f.y, hq.w + a1.f.y);
                if (lane < 3) {
                    float cnt = g_cnt[n1];
                    if (cnt < 1.0f) cnt = 1.0f;
                    g_x[n1 * 3 + lane] += g_cagg[n1 * 3 + lane] / cnt;
                    g_cagg[n1 * 3 + lane] = 0.0f;
                }
            }
        }
        __syncwarp();
    }
}

// ---------------- head ---------------------------------------------------------
#define H_OFF_EW   0
#define H_OFF_HW1  4096
#define H_OFF_HW2  8192
#define H_OFF_EB   9472
#define H_OFF_HB1  9536
#define H_OFF_HB2  9600
#define H_OFF_FEAT 9620
#define H_SMEM_FLOATS 10132

__global__ __launch_bounds__(256) void head_kernel(
    const float* __restrict__ EW, const float* __restrict__ EB,
    const float* __restrict__ HW1, const float* __restrict__ HB1,
    const float* __restrict__ HW2, const float* __restrict__ HB2,
    float* __restrict__ out)
{
    extern __shared__ float s[];
    float* sEW  = s + H_OFF_EW;
    float* sHW1 = s + H_OFF_HW1;
    float* sHW2 = s + H_OFF_HW2;
    float* sEB  = s + H_OFF_EB;
    float* sHB1 = s + H_OFF_HB1;
    float* sHB2 = s + H_OFF_HB2;

    int tid = threadIdx.x;
    for (int i = tid; i < 4096; i += 256) { sEW[i] = EW[i]; sHW1[i] = HW1[i]; }
    for (int i = tid; i < 1280; i += 256) sHW2[i] = HW2[i];
    if (tid < 64) { sEB[tid] = EB[tid]; sHB1[tid] = HB1[tid]; }
    if (tid < 20) sHB2[tid] = HB2[tid];
    __syncthreads();

    int lane = tid & 31;
    int wloc = tid >> 5;
    float* fw = s + H_OFF_FEAT + wloc * 64;

    int warp   = (blockIdx.x * blockDim.x + tid) >> 5;
    int nwarps = (gridDim.x * blockDim.x) >> 5;

    for (int n = warp; n < N_NODES; n += nwarps) {
        float h0 = g_h[n * HID + lane], h1 = g_h[n * HID + 32 + lane];
        fw[lane] = h0; fw[32 + lane] = h1;
        __syncwarp();

        float t0 = sEB[lane], t1 = sEB[32 + lane];
        #pragma unroll 8
        for (int k = 0; k < 64; k++) {
            float f = fw[k];
            t0 = fmaf(f, sEW[k * 64 + lane], t0);
            t1 = fmaf(f, sEW[k * 64 + 32 + lane], t1);
        }
        __syncwarp();
        fw[lane] = t0; fw[32 + lane] = t1;
        __syncwarp();

        float r0 = sHB1[lane], r1 = sHB1[32 + lane];
        #pragma unroll 8
        for (int k = 0; k < 64; k++) {
            float f = fw[k];
            r0 = fmaf(f, sHW1[k * 64 + lane], r0);
            r1 = fmaf(f, sHW1[k * 64 + 32 + lane], r1);
        }
        r0 = fmaxf(r0, 0.0f); r1 = fmaxf(r1, 0.0f);
        __syncwarp();
        fw[lane] = r0; fw[32 + lane] = r1;
        __syncwarp();

        if (lane < OUT_NF) {
            float o = sHB2[lane];
            #pragma unroll 8
            for (int k = 0; k < 64; k++)
                o = fmaf(fw[k], sHW2[k * OUT_NF + lane], o);
            out[n * OUT_NF + lane] = o;
        }
        __syncwarp();
    }
}

// ---------------- launcher ----------------------------------------------------
extern "C" void kernel_launch(void* const* d_in, const int* in_sizes, int n_in,
                              void* d_out, int out_size) {
    const float* h_in      = (const float*)d_in[0];
    const float* x_in      = (const float*)d_in[1];
    const int*   edges     = (const int*)d_in[2];
    const float* emb_in_w  = (const float*)d_in[3];
    const float* emb_in_b  = (const float*)d_in[4];
    const float* emb_out_w = (const float*)d_in[5];
    const float* emb_out_b = (const float*)d_in[6];
    const float* edge_w1   = (const float*)d_in[7];
    const float* edge_b1   = (const float*)d_in[8];
    const float* edge_w2   = (const float*)d_in[9];
    const float* edge_b2   = (const float*)d_in[10];
    const float* node_w1   = (const float*)d_in[11];
    const float* node_b1   = (const float*)d_in[12];
    const float* node_w2   = (const float*)d_in[13];
    const float* node_b2   = (const float*)d_in[14];
    const float* coord_w1  = (const float*)d_in[15];
    const float* coord_b1  = (const float*)d_in[16];
    const float* coord_w2  = (const float*)d_in[17];
    const float* head_w1   = (const float*)d_in[18];
    const float* head_b1   = (const float*)d_in[19];
    const float* head_w2   = (const float*)d_in[20];
    const float* head_b2   = (const float*)d_in[21];
    float* out = (float*)d_out;

    cudaFuncSetAttribute(edge_mma_kernel, cudaFuncAttributeMaxDynamicSharedMemorySize,
                         SM_TOTAL_E);
    cudaFuncSetAttribute(node_kernel, cudaFuncAttributeMaxDynamicSharedMemorySize,
                         N_SMEM_FLOATS * sizeof(float));
    cudaFuncSetAttribute(head_kernel, cudaFuncAttributeMaxDynamicSharedMemorySize,
                         H_SMEM_FLOATS * sizeof(float));

    const int* row = edges;
    const int* col = edges + N_EDGES;

    init_kernel<<<2048, 256>>>(x_in);
    embed_kernel<<<(N_NODES * HID + 255) / 256, 256>>>(h_in, emb_in_w, emb_in_b);
    count_kernel<<<(N_EDGES + 255) / 256, 256>>>(row);

    for (int l = 0; l < N_LAYERS; l++) {
        edge_mma_kernel<<<EK_GRID, EK_THREADS, SM_TOTAL_E>>>(
            row, col,
            edge_w1 + l * (2 * HID + 1) * HID, edge_b1 + l * HID,
            edge_w2 + l * HID * HID, edge_b2 + l * HID,
            coord_w1 + l * HID * HID, coord_b1 + l * HID,
            coord_w2 + l * HID);
        node_kernel<<<GRID_PERSIST, CTA_THREADS, N_SMEM_FLOATS * sizeof(float)>>>(
            node_w1 + l * 2 * HID * HID, node_b1 + l * HID,
            node_w2 + l * HID * HID, node_b2 + l * HID);
    }

    head_kernel<<<6250, 256, H_SMEM_FLOATS * sizeof(float)>>>(
        emb_out_w, emb_out_b, head_w1, head_b1, head_w2, head_b2, out);
}

// round 11
// speedup vs baseline: 2.1035x; 1.3661x over previous
#include <cuda_runtime.h>
#include <cuda_bf16.h>
#include <cstdint>

#define N_NODES 50000
#define N_EDGES 800000
#define IN_NF 21
#define HID 64
#define OUT_NF 20
#define N_LAYERS 4

// ---------------- scratch (device globals; no runtime allocation) -------------
__device__ float g_h[N_NODES * HID];
__device__ float g_x[N_NODES * 3];
__device__ float g_cnt[N_NODES];
__device__ float g_agg[N_NODES * HID];
__device__ float g_cagg[N_NODES * 3];

__device__ __forceinline__ float silu(float v) {
    return v / (1.0f + __expf(-v));
}

#define SWZ(off) ((off) ^ (((off) >> 3) & 0x70))

__device__ __forceinline__ uint32_t smem_u32(const void* p) {
    uint32_t a;
    asm("{ .reg .u64 t; cvta.to.shared.u64 t, %1; cvt.u32.u64 %0, t; }"
        : "=r"(a) : "l"(p));
    return a;
}

// pack two fp32 -> bf16x2 (v0 -> low 16 bits)
__device__ __forceinline__ uint32_t bf16x2_pack(float v0, float v1) {
    uint32_t r;
    asm("cvt.rn.bf16x2.f32 %0, %1, %2;" : "=r"(r) : "f"(v1), "f"(v0));
    return r;
}
__device__ __forceinline__ void split2(float v0, float v1, uint32_t& h, uint32_t& l) {
    h = bf16x2_pack(v0, v1);
    float h0 = __uint_as_float(h << 16);
    float h1 = __uint_as_float(h & 0xFFFF0000u);
    l = bf16x2_pack(v0 - h0, v1 - h1);
}

__device__ __forceinline__ void ldsm4(uint32_t addr, uint32_t r[4]) {
    asm volatile("ldmatrix.sync.aligned.m8n8.x4.shared.b16 {%0,%1,%2,%3}, [%4];"
        : "=r"(r[0]), "=r"(r[1]), "=r"(r[2]), "=r"(r[3]) : "r"(addr));
}
__device__ __forceinline__ void mma16816(float* c, const uint32_t* a, const uint32_t* b) {
    asm volatile(
        "mma.sync.aligned.m16n8k16.row.col.f32.bf16.bf16.f32 "
        "{%0,%1,%2,%3}, {%4,%5,%6,%7}, {%8,%9}, {%0,%1,%2,%3};"
        : "+f"(c[0]), "+f"(c[1]), "+f"(c[2]), "+f"(c[3])
        : "r"(a[0]), "r"(a[1]), "r"(a[2]), "r"(a[3]), "r"(b[0]), "r"(b[1]));
}

// named pair barrier: 64 threads (one warp pair)
#define BAR_PAIR(id) asm volatile("bar.sync %0, 64;" :: "r"(id) : "memory")

// ---------------- small kernels ------------------------------------------------
__global__ void init_kernel(const float* __restrict__ x_in) {
    int stride = gridDim.x * blockDim.x;
    int t0 = blockIdx.x * blockDim.x + threadIdx.x;
    for (int i = t0; i < N_NODES * HID; i += stride) g_agg[i] = 0.0f;
    for (int i = t0; i < N_NODES * 3; i += stride) { g_x[i] = x_in[i]; g_cagg[i] = 0.0f; }
    for (int i = t0; i < N_NODES; i += stride) g_cnt[i] = 0.0f;
}

__global__ void embed_kernel(const float* __restrict__ h_in,
                             const float* __restrict__ W,
                             const float* __restrict__ b) {
    int i = blockIdx.x * blockDim.x + threadIdx.x;
    if (i >= N_NODES * HID) return;
    int n = i >> 6;
    int c = i & 63;
    const float* hr = h_in + n * IN_NF;
    float acc = b[c];
    #pragma unroll
    for (int k = 0; k < IN_NF; k++) acc = fmaf(hr[k], W[k * HID + c], acc);
    g_h[i] = acc;
}

__global__ void count_kernel(const int* __restrict__ row) {
    int e = blockIdx.x * blockDim.x + threadIdx.x;
    if (e < N_EDGES) atomicAdd(&g_cnt[row[e]], 1.0f);
}

// ================= edge kernel: mma.sync bf16, 128-edge tiles ==================
// smem byte offsets; all panels [rows][64] bf16, 128B/row, SW128 swizzled.
#define SM_W1A_HI  0
#define SM_W1A_LO  8192
#define SM_W1B_HI  16384
#define SM_W1B_LO  24576
#define SM_W2_HI   32768
#define SM_W2_LO   40960
#define SM_CW1_HI  49152
#define SM_CW1_LO  57344
#define SM_A1R_HI  65536
#define SM_A1R_LO  81920
#define SM_A1C_HI  98304
#define SM_A1C_LO  114688
#define SM_A2_HI   131072
#define SM_A2_LO   147456
#define SM_EP1     163840
#define SM_B2F     164352
#define SM_EP3     164608
#define SM_RAD     165120
#define SM_RIDX    165632
#define SM_DIFF    166144
#define SM_TOTAL_E 167680

#define EK_THREADS 512
#define E_TILES (N_EDGES / 128)   // 6250 exact
#define EK_GRID 152

// 3-pass split-bf16 GEMM over one K=64 panel, HALF of the n dimension.
// A panel: [128 rows][64 k]; B panel: [64 n][64 k]. Warp handles the 16 rows
// [mBase, mBase+16) and 32 columns [nOff32*... ] selected via nRowOff (= 32*(wid&1)
// added to the B row index). c[4][4] fragments (local nt 0..3).
// LDSM hoisted: aH, aL, bH, bL loaded once per kt; 12 MMAs from regs.
__device__ __forceinline__ void gemm_panel_half(float c[4][4],
                                                uint32_t aHi, uint32_t aLo,
                                                uint32_t bHi, uint32_t bLo,
                                                int mBase, int nRowOff, int lane) {
    int g = lane >> 3, r = lane & 7;
    int aRow  = mBase + ((g & 1) << 3) + r;
    int aKoff = (g >> 1) << 4;                  // 0 / 16 bytes
    int bRow  = ((g >> 1) << 3) + r + nRowOff;  // + j*16
    int bKoff = (g & 1) << 4;
    #pragma unroll
    for (int kt = 0; kt < 4; kt++) {
        int kb = kt << 5;                       // 32 bytes per k16
        uint32_t aH[4], aL[4], bH[2][4], bL[2][4];
        uint32_t aOff = SWZ((uint32_t)(aRow * 128 + kb + aKoff));
        ldsm4(aHi + aOff, aH);
        ldsm4(aLo + aOff, aL);
        uint32_t b0 = SWZ((uint32_t)(bRow * 128 + kb + bKoff));
        uint32_t b1 = SWZ((uint32_t)((bRow + 16) * 128 + kb + bKoff));
        ldsm4(bHi + b0, bH[0]);
        ldsm4(bHi + b1, bH[1]);
        ldsm4(bLo + b0, bL[0]);
        ldsm4(bLo + b1, bL[1]);
        #pragma unroll
        for (int j = 0; j < 2; j++) {
            mma16816(c[2 * j],     aH, &bH[j][0]);
            mma16816(c[2 * j + 1], aH, &bH[j][2]);
            mma16816(c[2 * j],     aH, &bL[j][0]);
            mma16816(c[2 * j + 1], aH, &bL[j][2]);
            mma16816(c[2 * j],     aL, &bH[j][0]);
            mma16816(c[2 * j + 1], aL, &bH[j][2]);
        }
    }
}

__global__ __launch_bounds__(EK_THREADS, 1) void edge_mma_kernel(
    const int* __restrict__ row, const int* __restrict__ col,
    const float* __restrict__ W1, const float* __restrict__ B1,
    const float* __restrict__ W2, const float* __restrict__ B2,
    const float* __restrict__ CW1, const float* __restrict__ CB1,
    const float* __restrict__ CW2)
{
    extern __shared__ char smem[];
    uint32_t sb = smem_u32(smem);
    int tid   = threadIdx.x;
    int lane  = tid & 31;
    int wid   = tid >> 5;           // 16 warps: pair p = wid>>1 owns rows 16p..16p+16
    int pair  = wid >> 1;
    int nhalf = wid & 1;            // column half: nhalf*32 .. nhalf*32+32
    int wrow  = pair * 16;
    int nRowOff = nhalf * 32;
    int barId = 1 + pair;           // named barrier per pair (ids 1..8)

    // ---- stage weights transposed + split: panels [n][k] bf16, SW128 ----
    for (int idx = tid; idx < 8192; idx += EK_THREADS) {
        int k = idx >> 6, n = idx & 63;
        float v = W1[k * 64 + n];
        __nv_bfloat16 hb = __float2bfloat16(v);
        __nv_bfloat16 lb = __float2bfloat16(v - __bfloat162float(hb));
        uint32_t off = SWZ((uint32_t)(n * 128 + (k & 63) * 2));
        int bhi = (k < 64) ? SM_W1A_HI : SM_W1B_HI;
        int blo = (k < 64) ? SM_W1A_LO : SM_W1B_LO;
        *(__nv_bfloat16*)(smem + bhi + off) = hb;
        *(__nv_bfloat16*)(smem + blo + off) = lb;
    }
    for (int idx = tid; idx < 4096; idx += EK_THREADS) {
        int k = idx >> 6, n = idx & 63;
        uint32_t off = SWZ((uint32_t)(n * 128 + k * 2));
        {
            float v = W2[k * 64 + n];
            __nv_bfloat16 hb = __float2bfloat16(v);
            __nv_bfloat16 lb = __float2bfloat16(v - __bfloat162float(hb));
            *(__nv_bfloat16*)(smem + SM_W2_HI + off) = hb;
            *(__nv_bfloat16*)(smem + SM_W2_LO + off) = lb;
        }
        {
            float v = CW1[k * 64 + n];
            __nv_bfloat16 hb = __float2bfloat16(v);
            __nv_bfloat16 lb = __float2bfloat16(v - __bfloat162float(hb));
            *(__nv_bfloat16*)(smem + SM_CW1_HI + off) = hb;
            *(__nv_bfloat16*)(smem + SM_CW1_LO + off) = lb;
        }
    }
    if (tid < 64) {
        ((float2*)(smem + SM_EP1))[tid] = make_float2(B1[tid], W1[128 * 64 + tid]);
        ((float*)(smem + SM_B2F))[tid]  = B2[tid];
        ((float2*)(smem + SM_EP3))[tid] = make_float2(CB1[tid], CW2[tid]);
    }
    __syncthreads();

    const float2* ep1  = (const float2*)(smem + SM_EP1);
    const float*  b2f  = (const float*)(smem + SM_B2F);
    const float2* ep3  = (const float2*)(smem + SM_EP3);
    float* sRad  = (float*)(smem + SM_RAD);
    int*   sRidx = (int*)(smem + SM_RIDX);
    float* sDiff = (float*)(smem + SM_DIFF);

    int qr = lane >> 2;          // 0..7
    int qc = (lane & 3) << 1;    // col base within n8

    int erow = tid >> 2;         // four threads per edge row
    int q4   = tid & 3;

    // Rows [16p,16p+16) are staged by threads [64p,64p+64) = warp pair p, and
    // read only by pair p: pair barriers suffice; pairs pipeline independently.
    for (int tile = blockIdx.x; tile < E_TILES; tile += gridDim.x) {
        // ---- gather: 4 threads per edge ----
        {
            int e  = tile * 128 + erow;
            int rr = __ldg(&row[e]);
            int cc = __ldg(&col[e]);
            if (q4 == 0) {
                float d0 = __ldg(&g_x[rr * 3 + 0]) - __ldg(&g_x[cc * 3 + 0]);
                float d1 = __ldg(&g_x[rr * 3 + 1]) - __ldg(&g_x[cc * 3 + 1]);
                float d2 = __ldg(&g_x[rr * 3 + 2]) - __ldg(&g_x[cc * 3 + 2]);
                sRad[erow]  = d0 * d0 + d1 * d1 + d2 * d2;
                sRidx[erow] = rr;
                sDiff[erow * 3 + 0] = d0;
                sDiff[erow * 3 + 1] = d1;
                sDiff[erow * 3 + 2] = d2;
            }
            const float4* hr4 = (const float4*)(g_h + rr * 64);
            const float4* hc4 = (const float4*)(g_h + cc * 64);
            #pragma unroll
            for (int j = 0; j < 2; j++) {
                int jj = q4 * 2 + j;
                uint32_t off = SWZ((uint32_t)(erow * 128 + jj * 16));
                float4 f0 = __ldg(&hr4[2 * jj]);
                float4 f1 = __ldg(&hr4[2 * jj + 1]);
                uint32_t h0, h1, h2, h3, l0, l1, l2, l3;
                split2(f0.x, f0.y, h0, l0); split2(f0.z, f0.w, h1, l1);
                split2(f1.x, f1.y, h2, l2); split2(f1.z, f1.w, h3, l3);
                *(uint4*)(smem + SM_A1R_HI + off) = make_uint4(h0, h1, h2, h3);
                *(uint4*)(smem + SM_A1R_LO + off) = make_uint4(l0, l1, l2, l3);
                f0 = __ldg(&hc4[2 * jj]);
                f1 = __ldg(&hc4[2 * jj + 1]);
                split2(f0.x, f0.y, h0, l0); split2(f0.z, f0.w, h1, l1);
                split2(f1.x, f1.y, h2, l2); split2(f1.z, f1.w, h3, l3);
                *(uint4*)(smem + SM_A1C_HI + off) = make_uint4(h0, h1, h2, h3);
                *(uint4*)(smem + SM_A1C_LO + off) = make_uint4(l0, l1, l2, l3);
            }
        }
        BAR_PAIR(barId);

        float c[4][4];

        // ---- GEMM1: feat @ W1 (two K=64 panels), this warp's column half ----
        #pragma unroll
        for (int nt = 0; nt < 4; nt++)
            #pragma unroll
            for (int q = 0; q < 4; q++) c[nt][q] = 0.0f;
        gemm_panel_half(c, sb + SM_A1R_HI, sb + SM_A1R_LO,
                        sb + SM_W1A_HI, sb + SM_W1A_LO, wrow, nRowOff, lane);
        gemm_panel_half(c, sb + SM_A1C_HI, sb + SM_A1C_LO,
                        sb + SM_W1B_HI, sb + SM_W1B_LO, wrow, nRowOff, lane);

        // ---- epi1: m1 = silu(C + rad*w1r + b1) -> A2 (own column half) ----
        {
            int rowA = wrow + qr;
            int rowB = rowA + 8;
            float radA = sRad[rowA], radB = sRad[rowB];
            #pragma unroll
            for (int nt = 0; nt < 4; nt++) {
                int c0 = nhalf * 32 + nt * 8 + qc;
                float2 e0 = ep1[c0], e1 = ep1[c0 + 1];
                float v0 = silu(c[nt][0] + radA * e0.y + e0.x);
                float v1 = silu(c[nt][1] + radA * e1.y + e1.x);
                float v2 = silu(c[nt][2] + radB * e0.y + e0.x);
                float v3 = silu(c[nt][3] + radB * e1.y + e1.x);
                uint32_t h, l;
                split2(v0, v1, h, l);
                *(uint32_t*)(smem + SM_A2_HI + SWZ((uint32_t)(rowA * 128 + c0 * 2))) = h;
                *(uint32_t*)(smem + SM_A2_LO + SWZ((uint32_t)(rowA * 128 + c0 * 2))) = l;
                split2(v2, v3, h, l);
                *(uint32_t*)(smem + SM_A2_HI + SWZ((uint32_t)(rowB * 128 + c0 * 2))) = h;
                *(uint32_t*)(smem + SM_A2_LO + SWZ((uint32_t)(rowB * 128 + c0 * 2))) = l;
            }
        }
        BAR_PAIR(barId);

        // ---- GEMM2: m1 @ W2 ----
        #pragma unroll
        for (int nt = 0; nt < 4; nt++)
            #pragma unroll
            for (int q = 0; q < 4; q++) c[nt][q] = 0.0f;
        gemm_panel_half(c, sb + SM_A2_HI, sb + SM_A2_LO,
                        sb + SM_W2_HI, sb + SM_W2_LO, wrow, nRowOff, lane);
        BAR_PAIR(barId);   // pair done reading A2 before overwrite

        // ---- epi2: m = silu(C + b2); atomics into g_agg; restage A2 ----
        {
            int rowA = wrow + qr;
            int rowB = rowA + 8;
            float* aggA = g_agg + sRidx[rowA] * 64;
            float* aggB = g_agg + sRidx[rowB] * 64;
            #pragma unroll
            for (int nt = 0; nt < 4; nt++) {
                int c0 = nhalf * 32 + nt * 8 + qc;
                float b0 = b2f[c0], b1 = b2f[c0 + 1];
                float v0 = silu(c[nt][0] + b0);
                float v1 = silu(c[nt][1] + b1);
                float v2 = silu(c[nt][2] + b0);
                float v3 = silu(c[nt][3] + b1);
                atomicAdd(&aggA[c0], v0);
                atomicAdd(&aggA[c0 + 1], v1);
                atomicAdd(&aggB[c0], v2);
                atomicAdd(&aggB[c0 + 1], v3);
                uint32_t h, l;
                split2(v0, v1, h, l);
                *(uint32_t*)(smem + SM_A2_HI + SWZ((uint32_t)(rowA * 128 + c0 * 2))) = h;
                *(uint32_t*)(smem + SM_A2_LO + SWZ((uint32_t)(rowA * 128 + c0 * 2))) = l;
                split2(v2, v3, h, l);
                *(uint32_t*)(smem + SM_A2_HI + SWZ((uint32_t)(rowB * 128 + c0 * 2))) = h;
                *(uint32_t*)(smem + SM_A2_LO + SWZ((uint32_t)(rowB * 128 + c0 * 2))) = l;
            }
        }
        BAR_PAIR(barId);

        // ---- GEMM3: m @ CW1 ----
        #pragma unroll
        for (int nt = 0; nt < 4; nt++)
            #pragma unroll
            for (int q = 0; q < 4; q++) c[nt][q] = 0.0f;
        gemm_panel_half(c, sb + SM_A2_HI, sb + SM_A2_LO,
                        sb + SM_CW1_HI, sb + SM_CW1_LO, wrow, nRowOff, lane);

        // ---- epi3: partial sc over own columns; coord atomics (additive) ----
        {
            float pA = 0.0f, pB = 0.0f;
            #pragma unroll
            for (int nt = 0; nt < 4; nt++) {
                int c0 = nhalf * 32 + nt * 8 + qc;
                float2 e0 = ep3[c0], e1 = ep3[c0 + 1];
                pA += silu(c[nt][0] + e0.x) * e0.y + silu(c[nt][1] + e1.x) * e1.y;
                pB += silu(c[nt][2] + e0.x) * e0.y + silu(c[nt][3] + e1.x) * e1.y;
            }
            pA += __shfl_xor_sync(0xFFFFFFFFu, pA, 1);
            pA += __shfl_xor_sync(0xFFFFFFFFu, pA, 2);
            pB += __shfl_xor_sync(0xFFFFFFFFu, pB, 1);
            pB += __shfl_xor_sync(0xFFFFFFFFu, pB, 2);
            if ((lane & 3) == 0) {
                int rowA = wrow + qr;
                int rowB = rowA + 8;
                int rA = sRidx[rowA], rB = sRidx[rowB];
                atomicAdd(&g_cagg[rA * 3 + 0], sDiff[rowA * 3 + 0] * pA);
                atomicAdd(&g_cagg[rA * 3 + 1], sDiff[rowA * 3 + 1] * pA);
                atomicAdd(&g_cagg[rA * 3 + 2], sDiff[rowA * 3 + 2] * pA);
                atomicAdd(&g_cagg[rB * 3 + 0], sDiff[rowB * 3 + 0] * pB);
                atomicAdd(&g_cagg[rB * 3 + 1], sDiff[rowB * 3 + 1] * pB);
                atomicAdd(&g_cagg[rB * 3 + 2], sDiff[rowB * 3 + 2] * pB);
            }
        }
        BAR_PAIR(barId);   // before next tile's gather overwrites A1/meta
    }
}

// ================= node kernel (fp32 pair-packed; zeroes agg after use) ========
#define EPW 8
#define CTA_THREADS 512
#define WARPS_CTA 16
#define TILE_E (EPW * WARPS_CTA)
#define NODE_TILES ((N_NODES + TILE_E - 1) / TILE_E)
#define GRID_PERSIST 152

typedef unsigned long long ull;
union F2u { ull u; float2 f; };

__device__ __forceinline__ ull splat2(float v) {
    ull r; asm("mov.b64 %0, {%1, %1};" : "=l"(r) : "f"(v)); return r;
}
__device__ __forceinline__ void ffma2(ull& a, ull x, ull y) {
    asm("fma.rn.f32x2 %0, %1, %2, %0;" : "+l"(a) : "l"(x), "l"(y));
}

template<int K, int STRIDE>
__device__ __forceinline__ void gemm_pair(ull acc[4][2], const float* __restrict__ W,
                                          const float* __restrict__ fp, int lane) {
    #pragma unroll 4
    for (int k = 0; k < K; k += 2) {
        float2 w0 = ((const float2*)(W + k * 64))[lane];
        float2 w1 = ((const float2*)(W + (k + 1) * 64))[lane];
        ull w00 = splat2(w0.x), w01 = splat2(w0.y);
        ull w10 = splat2(w1.x), w11 = splat2(w1.y);
        #pragma unroll
        for (int p = 0; p < 4; p++) {
            ulonglong2 f = *(const ulonglong2*)(fp + p * STRIDE + 2 * k);
            ffma2(acc[p][0], f.x, w00);
            ffma2(acc[p][1], f.x, w01);
            ffma2(acc[p][0], f.y, w10);
            ffma2(acc[p][1], f.y, w11);
        }
    }
}

#define NPS 260
#define UPS 132
#define N_OFF_W1   0
#define N_OFF_W2   8192
#define N_OFF_B1   12288
#define N_OFF_B2   12352
#define N_OFF_FEAT 12416
#define N_OFF_U    (N_OFF_FEAT + WARPS_CTA * 4 * NPS)
#define N_SMEM_FLOATS (N_OFF_U + WARPS_CTA * 4 * UPS)

__global__ __launch_bounds__(CTA_THREADS, 1) void node_kernel(
    const float* __restrict__ W1, const float* __restrict__ B1,
    const float* __restrict__ W2, const float* __restrict__ B2)
{
    extern __shared__ float s[];
    float* sW1 = s + N_OFF_W1;
    float* sW2 = s + N_OFF_W2;
    float* sB1 = s + N_OFF_B1;
    float* sB2 = s + N_OFF_B2;

    int tid = threadIdx.x;
    for (int i = tid; i < 8192; i += CTA_THREADS) sW1[i] = W1[i];
    for (int i = tid; i < 4096; i += CTA_THREADS) sW2[i] = W2[i];
    if (tid < 64) { sB1[tid] = B1[tid]; sB2[tid] = B2[tid]; }
    __syncthreads();

    int lane = tid & 31;
    int wid  = tid >> 5;
    float* fw = s + N_OFF_FEAT + wid * (4 * NPS);
    float* uw = s + N_OFF_U    + wid * (4 * UPS);

    float2 b1v = ((const float2*)sB1)[lane];
    float2 b2v = ((const float2*)sB2)[lane];

    for (int tile = blockIdx.x; tile < NODE_TILES; tile += gridDim.x) {
        int nbase = tile * TILE_E + wid * EPW;

        #pragma unroll
        for (int e = 0; e < EPW; e++) {
            int n = nbase + e;
            if (n < N_NODES) {
                float* fpq = fw + (e >> 1) * NPS + (e & 1);
                fpq[2 * lane]       = g_h[n * HID + lane];
                fpq[64 + 2 * lane]  = g_h[n * HID + 32 + lane];
                fpq[128 + 2 * lane] = g_agg[n * HID + lane];
                fpq[192 + 2 * lane] = g_agg[n * HID + 32 + lane];
                // re-zero aggregation for the next layer's edge pass
                g_agg[n * HID + lane] = 0.0f;
                g_agg[n * HID + 32 + lane] = 0.0f;
            }
        }
        __syncwarp();

        ull acc[4][2];
        #pragma unroll
        for (int p = 0; p < 4; p++) { acc[p][0] = splat2(b1v.x); acc[p][1] = splat2(b1v.y); }
        gemm_pair<128, NPS>(acc, sW1, fw, lane);
        #pragma unroll
        for (int p = 0; p < 4; p++) {
            F2u a0, a1; a0.u = acc[p][0]; a1.u = acc[p][1];
            a0.f.x = silu(a0.f.x); a0.f.y = silu(a0.f.y);
            a1.f.x = silu(a1.f.x); a1.f.y = silu(a1.f.y);
            *(ulonglong2*)(uw + p * UPS + 4 * lane) = make_ulonglong2(a0.u, a1.u);
        }
        __syncwarp();

        #pragma unroll
        for (int p = 0; p < 4; p++) { acc[p][0] = splat2(b2v.x); acc[p][1] = splat2(b2v.y); }
        gemm_pair<64, UPS>(acc, sW2, uw, lane);

        #pragma unroll
        for (int p = 0; p < 4; p++) {
            F2u a0, a1; a0.u = acc[p][0]; a1.u = acc[p][1];
            float4 hq = *(const float4*)(fw + p * NPS + 4 * lane);
            int n0 = nbase + 2 * p, n1 = n0 + 1;
            if (n0 < N_NODES) {
                ((float2*)(g_h + n0 * HID))[lane] =
                    make_float2(hq.x + a0.f.x, hq.z + a1.f.x);
                if (lane < 3) {
                    float cnt = g_cnt[n0];
                    if (cnt < 1.0f) cnt = 1.0f;
                    g_x[n0 * 3 + lane] += g_cagg[n0 * 3 + lane] / cnt;
                    g_cagg[n0 * 3 + lane] = 0.0f;
                }
            }
            if (n1 < N_NODES) {
                ((float2*)(g_h + n1 * HID))[lane] =
                    make_float2(hq.y + a0.f.y, hq.w + a1.f.y);
                if (lane < 3) {
                    float cnt = g_cnt[n1];
                    if (cnt < 1.0f) cnt = 1.0f;
                    g_x[n1 * 3 + lane] += g_cagg[n1 * 3 + lane] / cnt;
                    g_cagg[n1 * 3 + lane] = 0.0f;
                }
            }
        }
        __syncwarp();
    }
}

// ---------------- head ---------------------------------------------------------
#define H_OFF_EW   0
#define H_OFF_HW1  4096
#define H_OFF_HW2  8192
#define H_OFF_EB   9472
#define H_OFF_HB1  9536
#define H_OFF_HB2  9600
#define H_OFF_FEAT 9620
#define H_SMEM_FLOATS 10132

__global__ __launch_bounds__(256) void head_kernel(
    const float* __restrict__ EW, const float* __restrict__ EB,
    const float* __restrict__ HW1, const float* __restrict__ HB1,
    const float* __restrict__ HW2, const float* __restrict__ HB2,
    float* __restrict__ out)
{
    extern __shared__ float s[];
    float* sEW  = s + H_OFF_EW;
    float* sHW1 = s + H_OFF_HW1;
    float* sHW2 = s + H_OFF_HW2;
    float* sEB  = s + H_OFF_EB;
    float* sHB1 = s + H_OFF_HB1;
    float* sHB2 = s + H_OFF_HB2;

    int tid = threadIdx.x;
    for (int i = tid; i < 4096; i += 256) { sEW[i] = EW[i]; sHW1[i] = HW1[i]; }
    for (int i = tid; i < 1280; i += 256) sHW2[i] = HW2[i];
    if (tid < 64) { sEB[tid] = EB[tid]; sHB1[tid] = HB1[tid]; }
    if (tid < 20) sHB2[tid] = HB2[tid];
    __syncthreads();

    int lane = tid & 31;
    int wloc = tid >> 5;
    float* fw = s + H_OFF_FEAT + wloc * 64;

    int warp   = (blockIdx.x * blockDim.x + tid) >> 5;
    int nwarps = (gridDim.x * blockDim.x) >> 5;

    for (int n = warp; n < N_NODES; n += nwarps) {
        float h0 = g_h[n * HID + lane], h1 = g_h[n * HID + 32 + lane];
        fw[lane] = h0; fw[32 + lane] = h1;
        __syncwarp();

        float t0 = sEB[lane], t1 = sEB[32 + lane];
        #pragma unroll 8
        for (int k = 0; k < 64; k++) {
            float f = fw[k];
            t0 = fmaf(f, sEW[k * 64 + lane], t0);
            t1 = fmaf(f, sEW[k * 64 + 32 + lane], t1);
        }
        __syncwarp();
        fw[lane] = t0; fw[32 + lane] = t1;
        __syncwarp();

        float r0 = sHB1[lane], r1 = sHB1[32 + lane];
        #pragma unroll 8
        for (int k = 0; k < 64; k++) {
            float f = fw[k];
            r0 = fmaf(f, sHW1[k * 64 + lane], r0);
            r1 = fmaf(f, sHW1[k * 64 + 32 + lane], r1);
        }
        r0 = fmaxf(r0, 0.0f); r1 = fmaxf(r1, 0.0f);
        __syncwarp();
        fw[lane] = r0; fw[32 + lane] = r1;
        __syncwarp();

        if (lane < OUT_NF) {
            float o = sHB2[lane];
            #pragma unroll 8
            for (int k = 0; k < 64; k++)
                o = fmaf(fw[k], sHW2[k * OUT_NF + lane], o);
            out[n * OUT_NF + lane] = o;
        }
        __syncwarp();
    }
}

// ---------------- launcher ----------------------------------------------------
extern "C" void kernel_launch(void* const* d_in, const int* in_sizes, int n_in,
                              void* d_out, int out_size) {
    const float* h_in      = (const float*)d_in[0];
    const float* x_in      = (const float*)d_in[1];
    const int*   edges     = (const int*)d_in[2];
    const float* emb_in_w  = (const float*)d_in[3];
    const float* emb_in_b  = (const float*)d_in[4];
    const float* emb_out_w = (const float*)d_in[5];
    const float* emb_out_b = (const float*)d_in[6];
    const float* edge_w1   = (const float*)d_in[7];
    const float* edge_b1   = (const float*)d_in[8];
    const float* edge_w2   = (const float*)d_in[9];
    const float* edge_b2   = (const float*)d_in[10];
    const float* node_w1   = (const float*)d_in[11];
    const float* node_b1   = (const float*)d_in[12];
    const float* node_w2   = (const float*)d_in[13];
    const float* node_b2   = (const float*)d_in[14];
    const float* coord_w1  = (const float*)d_in[15];
    const float* coord_b1  = (const float*)d_in[16];
    const float* coord_w2  = (const float*)d_in[17];
    const float* head_w1   = (const float*)d_in[18];
    const float* head_b1   = (const float*)d_in[19];
    const float* head_w2   = (const float*)d_in[20];
    const float* head_b2   = (const float*)d_in[21];
    float* out = (float*)d_out;

    cudaFuncSetAttribute(edge_mma_kernel, cudaFuncAttributeMaxDynamicSharedMemorySize,
                         SM_TOTAL_E);
    cudaFuncSetAttribute(node_kernel, cudaFuncAttributeMaxDynamicSharedMemorySize,
                         N_SMEM_FLOATS * sizeof(float));
    cudaFuncSetAttribute(head_kernel, cudaFuncAttributeMaxDynamicSharedMemorySize,
                         H_SMEM_FLOATS * sizeof(float));

    const int* row = edges;
    const int* col = edges + N_EDGES;

    init_kernel<<<2048, 256>>>(x_in);
    embed_kernel<<<(N_NODES * HID + 255) / 256, 256>>>(h_in, emb_in_w, emb_in_b);
    count_kernel<<<(N_EDGES + 255) / 256, 256>>>(row);

    for (int l = 0; l < N_LAYERS; l++) {
        edge_mma_kernel<<<EK_GRID, EK_THREADS, SM_TOTAL_E>>>(
            row, col,
            edge_w1 + l * (2 * HID + 1) * HID, edge_b1 + l * HID,
            edge_w2 + l * HID * HID, edge_b2 + l * HID,
            coord_w1 + l * HID * HID, coord_b1 + l * HID,
            coord_w2 + l * HID);
        node_kernel<<<GRID_PERSIST, CTA_THREADS, N_SMEM_FLOATS * sizeof(float)>>>(
            node_w1 + l * 2 * HID * HID, node_b1 + l * HID,
            node_w2 + l * HID * HID, node_b2 + l * HID);
    }

    head_kernel<<<6250, 256, H_SMEM_FLOATS * sizeof(float)>>>(
        emb_out_w, emb_out_b, head_w1, head_b1, head_w2, head_b2, out);
}